// round 13
// baseline (speedup 1.0000x reference)
#include <cuda_runtime.h>
#include <cuda_bf16.h>
#include <cstdint>

#define TT 15
#define C1 6
#define F1 30
#define H1 252
#define HPADIN 256
#define HP 126
#define HPD 128
#define F2 250
#define NPIX (HP*HP)          /* 15876 */
#define NQ   (NPIX/4)         /* 3969 */
#define TAPS 270
#define POT_OFF 59535000u
#define WIN_OFF 119070000u
#define FULLMASK 0x3FFFFFFFu
#define NQUAD 14883750u       /* 3750 planes * 3969 int4 (one half) */

// ---------------- device scratch ----------------
__device__ uint8_t  g_hs[TT*HPADIN*HPADIN];
__device__ uint32_t g_bits[TT*C1*HPADIN*8];
__device__ uint32_t g_pmask[TT*HPD*HPD];
__device__ float    g_w2t[TAPS*256];
__device__ float    g_S[256];
__device__ float    g_minwf[F1], g_maxwf[F1];
__device__ float    g_minwA, g_maxwA;
__device__ int      g_allpos;
__device__ float    g_iMaxv;
__device__ int      g_iMaxi;
__device__ float    g_maxv[TT*NPIX];
__device__ int      g_maxi[TT*NPIX];
__device__ float    g_pv[TT*NPIX];
__device__ int      g_win[NPIX];
__device__ __align__(16) uint8_t g_win8[NPIX+16];
__device__ float    g_val[NPIX];
__device__ float    g_total[NPIX];
__device__ int      g_list[TT*NPIX];
__device__ int      g_count;

// ---------------- K Fuse0: zero pmask + w1 stats + w2 transpose + S/argmax ----------------
__global__ void kFuse0(const float* __restrict__ w1, const float* __restrict__ w2) {
    __shared__ float smn[F1], smx[F1];
    __shared__ float rv[256];
    __shared__ int   ri[256];
    int b = blockIdx.x, tid = threadIdx.x;
    if (b < 240) {                                   // 240*256 int4 = sizeof(g_pmask)/16
        int i = b * 256 + tid;
        ((int4*)g_pmask)[i] = make_int4(0, 0, 0, 0);
        if (i == 0) g_count = 0;
        return;
    }
    if (b == 240) {                                  // w1 per-feature + global min/max
        if (tid < F1) {
            float mn = 1e30f, mx = -1e30f;
            for (int i = 0; i < 150; i++) {
                float w = w1[tid * 150 + i];
                mn = fminf(mn, w); mx = fmaxf(mx, w);
            }
            g_minwf[tid] = mn; g_maxwf[tid] = mx;
            smn[tid] = mn; smx[tid] = mx;
        }
        __syncthreads();
        if (tid == 0) {
            float mn = 1e30f, mx = -1e30f;
            for (int i = 0; i < F1; i++) { mn = fminf(mn, smn[i]); mx = fmaxf(mx, smx[i]); }
            g_minwA = mn; g_maxwA = mx; g_allpos = (mn > 0.f) ? 1 : 0;
        }
        return;
    }
    if (b == 511) {                                  // S[f] + interior first-argmax (direct w2)
        float s = 0.f;
        if (tid < F2) {
            const float* row = w2 + (size_t)tid * TAPS;
#pragma unroll 6
            for (int t = 0; t < TAPS; t++) s += row[t];   // tap-ascending == kPrep2 order
        }
        g_S[tid] = (tid < F2) ? s : 0.f;
        float sf = (tid < F2 && s > 10.f) ? s : 0.f;
        rv[tid] = sf; ri[tid] = tid;
        __syncthreads();
        for (int st = 128; st >= 1; st >>= 1) {
            if (tid < st) {
                float o = rv[tid + st]; int oi = ri[tid + st];
                if (o > rv[tid] || (o == rv[tid] && oi < ri[tid])) { rv[tid] = o; ri[tid] = oi; }
            }
            __syncthreads();
        }
        if (tid == 0) { g_iMaxv = rv[0]; g_iMaxi = ri[0]; }
        return;
    }
    int tap = b - 241;                               // 0..269: w2 transpose
    g_w2t[tap * 256 + tid] = (tid < F2) ? w2[tid * TAPS + tap] : 0.0f;
}

// ---------------- K A1: channel sums -> horizontal 5-sums + packed bits ----------------
__global__ void kA1(const int* __restrict__ inp) {
    __shared__ uint8_t scs[264];
    int bid = blockIdx.x;
    int t = bid >> 8, py = bid & 255;
    int px = threadIdx.x;
    int iy = py - 2, ix = px - 2;
    bool inr = (iy >= 0 && iy < H1 && ix >= 0 && ix < H1);
    int sum = 0;
    int bits[C1];
#pragma unroll
    for (int c = 0; c < C1; c++) {
        int v = inr ? inp[(((t * C1 + c) * H1) + iy) * H1 + ix] : 0;
        bits[c] = v; sum += v;
    }
    scs[px] = (uint8_t)sum;
    if (px < 8) scs[256 + px] = 0;
#pragma unroll
    for (int c = 0; c < C1; c++) {
        unsigned m = __ballot_sync(0xFFFFFFFFu, bits[c]);
        if ((px & 31) == 0)
            g_bits[((t * C1 + c) * HPADIN + py) * 8 + (px >> 5)] = m;
    }
    __syncthreads();
    int hs = scs[px] + scs[px + 1] + scs[px + 2] + scs[px + 3] + scs[px + 4];
    g_hs[(t * HPADIN + py) * HPADIN + px] = (uint8_t)hs;
}

// ---------------- K A2: conv1 fire + maxpool -> spike bitmask ----------------
__global__ void __launch_bounds__(128) kA2(const float* __restrict__ w1) {
    __shared__ uint8_t  shs[12][68];
    __shared__ uint32_t sb[C1][12][4];
    __shared__ float    sminf[F1], smaxf[F1];
    int t = blockIdx.z;
    int px0 = blockIdx.x * 32, py0 = blockIdx.y * 4;
    int cx0 = px0 * 2, cy0 = py0 * 2;
    int tid = threadIdx.y * 32 + threadIdx.x;

    for (int i = tid; i < 12 * 68; i += 128) {
        int r = i / 68, cc = i % 68;
        int gr = cy0 + r, gc = cx0 + cc;
        uint8_t v = 0;
        if (gr < HPADIN && gc < HPADIN && cc < 65) v = g_hs[(t * HPADIN + gr) * HPADIN + gc];
        shs[r][cc] = v;
    }
    int wb = cx0 >> 5;
    for (int i = tid; i < C1 * 12 * 4; i += 128) {
        int c = i / 48, r = (i / 4) % 12, w = i & 3;
        int gr = cy0 + r, gw = wb + w;
        uint32_t v = 0;
        if (gr < HPADIN && gw < 8) v = g_bits[((t * C1 + c) * HPADIN + gr) * 8 + gw];
        sb[c][r][w] = v;
    }
    if (tid < F1) { sminf[tid] = g_minwf[tid]; smaxf[tid] = g_maxwf[tid]; }
    __syncthreads();

    int px = px0 + threadIdx.x, py = py0 + threadIdx.y;
    if (px >= HP || py >= HP) return;
    int lr = 2 * threadIdx.y, lc = 2 * threadIdx.x;

    int a0 = shs[lr + 0][lc], a1 = shs[lr + 1][lc], a2 = shs[lr + 2][lc];
    int a3 = shs[lr + 3][lc], a4 = shs[lr + 4][lc], a5 = shs[lr + 5][lc];
    int b0 = shs[lr + 0][lc + 1], b1 = shs[lr + 1][lc + 1], b2 = shs[lr + 2][lc + 1];
    int b3 = shs[lr + 3][lc + 1], b4 = shs[lr + 4][lc + 1], b5 = shs[lr + 5][lc + 1];
    int cnt[2][2];
    int am = a1 + a2 + a3 + a4, bm = b1 + b2 + b3 + b4;
    cnt[0][0] = a0 + am; cnt[1][0] = am + a5;
    cnt[0][1] = b0 + bm; cnt[1][1] = bm + b5;
    int maxcnt = max(max(cnt[0][0], cnt[0][1]), max(cnt[1][0], cnt[1][1]));

    bool ap = (g_allpos != 0);
    uint32_t* pm = &g_pmask[(t * HPD + py + 1) * HPD + (px + 1)];

    if (ap && g_minwA * maxcnt > 15.001f) { *pm = FULLMASK; return; }
    if (ap && g_maxwA * maxcnt < 14.999f) { *pm = 0u; return; }

    uint32_t mask = 0;
    for (int f = 0; f < F1; f++) {
        float mn = sminf[f], mx = smaxf[f];
        int pooled;
        if (ap && mn * maxcnt > 15.001f) pooled = 1;
        else if (ap && mx * maxcnt < 14.999f) pooled = 0;
        else {
            pooled = 0;
            for (int dy = 0; dy < 2 && !pooled; dy++)
                for (int dx = 0; dx < 2 && !pooled; dx++) {
                    float pot = 0.f;
                    int off = lc + dx;
                    int w = off >> 5, s = off & 31;
                    for (int ch = 0; ch < C1; ch++) {
#pragma unroll
                        for (int i = 0; i < 5; i++) {
                            uint32_t lo = sb[ch][lr + dy + i][w];
                            uint32_t hi = sb[ch][lr + dy + i][w + 1];
                            uint32_t ck = __funnelshift_r(lo, hi, s);
                            const float* wp = &w1[((f * C1 + ch) * 5 + i) * 5];
#pragma unroll
                            for (int j = 0; j < 5; j++)
                                if ((ck >> j) & 1) pot += __ldg(wp + j);
                        }
                    }
                    pooled = (pot > 15.f) ? 1 : 0;
                }
        }
        mask |= ((uint32_t)pooled) << f;
    }
    *pm = mask;
}

// ---------------- K B1: classify (t,pixel) full vs deficient ----------------
__global__ void kB1() {
    int i = blockIdx.x * 256 + threadIdx.x;
    if (i >= TT * NPIX) return;
    int t = i / NPIX, pix = i % NPIX;
    int y = pix / HP, x = pix % HP;
    int s = 0;
#pragma unroll
    for (int dy = 0; dy < 3; dy++) {
        const uint32_t* row = &g_pmask[(t * HPD + y + dy) * HPD + x];
        s += __popc(row[0]) + __popc(row[1]) + __popc(row[2]);
    }
    if (s == TAPS) {
        g_maxv[i] = g_iMaxv; g_maxi[i] = g_iMaxi;
    } else {
        int slot = atomicAdd(&g_count, 1);
        g_list[slot] = i;
    }
}

// ---------------- K B2: deficient (t,pixel): all-250 pot + first-argmax ----------------
__global__ void __launch_bounds__(256) kB2() {
    __shared__ uint32_t pmask[9];
    __shared__ float rv[256];
    __shared__ int   ri[256];
    int cnt = g_count;
    int f = threadIdx.x;
    for (int e = blockIdx.x; e < cnt; e += gridDim.x) {
        int id = g_list[e];
        int t = id / NPIX, pix = id % NPIX;
        int y = pix / HP, x = pix % HP;
        if (f < 9)
            pmask[f] = g_pmask[(t * HPD + y + f / 3) * HPD + x + f % 3];
        __syncthreads();
        float pot = g_S[f];
#pragma unroll
        for (int p = 0; p < 9; p++) {
            uint32_t mm = (~pmask[p]) & FULLMASK;
            while (mm) {
                int c = __ffs(mm) - 1; mm &= mm - 1;
                pot -= g_w2t[(c * 9 + p) * 256 + f];
            }
        }
        float pf = (f < F2 && pot > 10.f) ? pot : 0.f;
        rv[f] = pf; ri[f] = f;
        __syncthreads();
        for (int st = 128; st >= 1; st >>= 1) {
            if (f < st) {
                float o = rv[f + st]; int oi = ri[f + st];
                if (o > rv[f] || (o == rv[f] && oi < ri[f])) { rv[f] = o; ri[f] = oi; }
            }
            __syncthreads();
        }
        if (f == 0) { g_maxv[id] = rv[0]; g_maxi[id] = ri[0]; }
        __syncthreads();
    }
}

// ---------------- K B34: per-(t,pixel) pot of winning channel ----------------
__global__ void kB34() {
    int i = blockIdx.x * 256 + threadIdx.x;
    if (i >= TT * NPIX) return;
    int t = i / NPIX, pix = i % NPIX;

    int cntf = 0;
#pragma unroll
    for (int tt = 0; tt < TT; tt++) cntf += (g_maxv[tt * NPIX + pix] > 0.f) ? 1 : 0;
    int fired = (g_maxv[(TT - 1) * NPIX + pix] > 0.f) ? 1 : 0;
    int e = TT - cntf; e = e < 0 ? 0 : (e > TT - 1 ? TT - 1 : e);
    int win = g_maxi[e * NPIX + pix];
    if (t == 0) { g_win[pix] = win; g_win8[pix] = (uint8_t)win; }

    float pv = 0.f;
    if (fired) {
        int y = pix / HP, x = pix % HP;
        uint32_t m[9];
        int s = 0;
#pragma unroll
        for (int p = 0; p < 9; p++) {
            m[p] = g_pmask[(t * HPD + y + p / 3) * HPD + x + p % 3];
            s += __popc(m[p]);
        }
        float pot = g_S[win];
        if (s != TAPS) {
#pragma unroll
            for (int p = 0; p < 9; p++) {            // (p outer, c ascending) == kB2 order
                uint32_t mm = (~m[p]) & FULLMASK;
                while (mm) {
                    int c = __ffs(mm) - 1; mm &= mm - 1;
                    pot -= g_w2t[(c * 9 + p) * 256 + win];
                }
            }
        }
        pv = (pot > 10.f) ? pot : 0.f;
    }
    g_pv[i] = pv;
}

// ---------------- K W: flat fused zero-fill + winner write (R6-proven shape) ----------------
__global__ void __launch_bounds__(256) kWrite(float* __restrict__ out) {
    unsigned idx4 = blockIdx.x * 256u + threadIdx.x;   // int4 index within spk half
    if (idx4 >= NQUAD) return;
    unsigned plane = idx4 / 3969u;                     // t*250+f
    unsigned r = idx4 - plane * 3969u;
    unsigned pix = r * 4u;
    unsigned t = plane / F2;
    unsigned f = plane - t * F2;
    uchar4 w4 = *(const uchar4*)&g_win8[pix];
    float4 p4 = *(const float4*)&g_pv[t * NPIX + pix];
    bool h0 = (w4.x == f) && (p4.x > 0.f);
    bool h1 = (w4.y == f) && (p4.y > 0.f);
    bool h2 = (w4.z == f) && (p4.z > 0.f);
    bool h3 = (w4.w == f) && (p4.w > 0.f);
    float4 sv  = make_float4(h0 ? 1.f : 0.f, h1 ? 1.f : 0.f, h2 ? 1.f : 0.f, h3 ? 1.f : 0.f);
    float4 pvv = make_float4(h0 ? p4.x : 0.f, h1 ? p4.y : 0.f, h2 ? p4.z : 0.f, h3 ? p4.w : 0.f);
    size_t base = (size_t)idx4 * 4u;
    __stcs((float4*)(out + base), sv);
    __stcs((float4*)(out + POT_OFF + base), pvv);
}

// ---------------- K B56: fused totals + k-winners (single block, hidden under kWrite) ----------------
__global__ void __launch_bounds__(1024) kB56(float* __restrict__ outw) {
    __shared__ float sred[1024];
    __shared__ unsigned long long red[1024];
    __shared__ int winfo[3];
    __shared__ float sv_bcast;
    int tid = threadIdx.x;

    float vmax = 0.f;
    for (int k = 0; k < 16; k++) {
        int pix = tid * 16 + k;
        if (pix < NPIX) {
            int ns = 0;
#pragma unroll
            for (int t = 0; t < TT; t++) ns += (g_pv[t * NPIX + pix] > 0.f) ? 1 : 0;
            int e = TT - ns; e = e < 0 ? 0 : (e > TT - 1 ? TT - 1 : e);
            float val = g_pv[e * NPIX + pix];
            g_val[pix] = val;
            if (ns > 0) vmax = fmaxf(vmax, val);
        }
    }
    sred[tid] = vmax;
    __syncthreads();
    for (int st = 512; st >= 1; st >>= 1) {
        if (tid < st) sred[tid] = fmaxf(sred[tid], sred[tid + st]);
        __syncthreads();
    }
    if (tid == 0) sv_bcast = sred[0] * 15.0f;
    __syncthreads();
    float v = sv_bcast;

    for (int k = 0; k < 16; k++) {
        int pix = tid * 16 + k;
        if (pix < NPIX) {
            float w = g_val[pix] + v;
            float tot = 0.f;
#pragma unroll
            for (int t = 0; t < TT; t++)
                if (g_pv[t * NPIX + pix] > 0.f) tot += w;
            g_total[pix] = tot;
        }
    }
    __syncthreads();

    unsigned kill = 0;
    for (int r = 0; r < 8; r++) {
        unsigned long long best = 0;
        for (int k = 0; k < 16; k++) {
            int e = tid * 16 + k;
            if (e < NPIX && !((kill >> k) & 1u)) {
                float tv = g_total[e];
                if (tv > 0.f) {
                    unsigned flat = (unsigned)(g_win[e] * NPIX + e);
                    unsigned long long key =
                        ((unsigned long long)__float_as_uint(tv) << 32) | (0xFFFFFFFFu - flat);
                    if (key > best) best = key;
                }
            }
        }
        red[tid] = best;
        __syncthreads();
        for (int st = 512; st >= 1; st >>= 1) {
            if (tid < st) {
                unsigned long long o = red[tid + st];
                if (o > red[tid]) red[tid] = o;
            }
            __syncthreads();
        }
        if (tid == 0) {
            unsigned long long b = red[0];
            if (b == 0) {
                winfo[0] = -1;
                outw[r * 3] = -1.f; outw[r * 3 + 1] = -1.f; outw[r * 3 + 2] = -1.f;
            } else {
                unsigned flat = 0xFFFFFFFFu - (unsigned)(b & 0xFFFFFFFFu);
                int c = flat / NPIX, pix = flat % NPIX;
                winfo[0] = c; winfo[1] = pix / HP; winfo[2] = pix % HP;
                outw[r * 3] = (float)c;
                outw[r * 3 + 1] = (float)winfo[1];
                outw[r * 3 + 2] = (float)winfo[2];
            }
        }
        __syncthreads();
        int wc = winfo[0];
        if (wc >= 0) {
            int wy = winfo[1], wx = winfo[2];
            for (int k = 0; k < 16; k++) {
                int e = tid * 16 + k;
                if (e < NPIX) {
                    int y = e / HP, x = e % HP;
                    if (g_win[e] == wc || (abs(y - wy) <= 1 && abs(x - wx) <= 1))
                        kill |= (1u << k);
                }
            }
        }
        __syncthreads();
    }
}

// ---------------- host launcher: R6 topology, minimal nodes ----------------
extern "C" void kernel_launch(void* const* d_in, const int* in_sizes, int n_in,
                              void* d_out, int out_size) {
    const int*   inp = (const int*)d_in[0];
    const float* w1  = (const float*)d_in[2];
    const float* w2  = (const float*)d_in[3];
    float* out = (float*)d_out;

    cudaStream_t s2;
    cudaEvent_t evFork, evJoin;
    cudaStreamCreateWithFlags(&s2, cudaStreamNonBlocking);
    cudaEventCreateWithFlags(&evFork, cudaEventDisableTiming);
    cudaEventCreateWithFlags(&evJoin, cudaEventDisableTiming);

    kFuse0<<<512, 256>>>(w1, w2);
    kA1<<<TT * 256, 256>>>(inp);
    dim3 gA2(4, 32, TT), bA2(32, 4);
    kA2<<<gA2, bA2>>>(w1);
    kB1<<<(TT * NPIX + 255) / 256, 256>>>();
    kB2<<<4096, 256>>>();
    kB34<<<(TT * NPIX + 255) / 256, 256>>>();

    // fork: single-block winner tail hidden under the big write
    cudaEventRecord(evFork, 0);
    cudaStreamWaitEvent(s2, evFork, 0);
    kB56<<<1, 1024, 0, s2>>>(out + WIN_OFF);
    cudaEventRecord(evJoin, s2);

    kWrite<<<(NQUAD + 255) / 256, 256>>>(out);

    cudaStreamWaitEvent(0, evJoin, 0);

    cudaStreamDestroy(s2);
    cudaEventDestroy(evFork);
    cudaEventDestroy(evJoin);
}

// round 14
// speedup vs baseline: 1.2855x; 1.2855x over previous
#include <cuda_runtime.h>
#include <cuda_bf16.h>
#include <cstdint>

#define TT 15
#define C1 6
#define F1 30
#define H1 252
#define HPADIN 256
#define HP 126
#define HPD 128
#define F2 250
#define NPIX (HP*HP)          /* 15876 */
#define TAPS 270
#define POT_OFF 59535000u
#define WIN_OFF 119070000u
#define FULLMASK 0x3FFFFFFFu
#define NQUAD 14883750u       /* 3750 planes * 3969 int4 */

// ---------------- device scratch ----------------
__device__ uint8_t  g_hs[TT*HPADIN*HPADIN];          // horizontal 5-sums of channel sums
__device__ uint32_t g_bits[TT*C1*HPADIN*8];          // packed input bits (padded coords)
__device__ uint32_t g_pmask[TT*HPD*HPD];             // pooled+padded spike bitmask (bit c)
__device__ float    g_w2t[TAPS*256];
__device__ float    g_S[256];
__device__ float    g_minwf[F1], g_maxwf[F1];
__device__ float    g_minwA, g_maxwA;
__device__ int      g_allpos;
__device__ float    g_iMaxv;
__device__ int      g_iMaxi;
__device__ float    g_maxv[TT*NPIX];
__device__ int      g_maxi[TT*NPIX];
__device__ float    g_pv[TT*NPIX];
__device__ int      g_win[NPIX];
__device__ uint8_t  g_fired[NPIX];
__device__ float    g_val[NPIX];
__device__ float    g_total[NPIX];
__device__ int      g_list[TT*NPIX];
__device__ int      g_count;
__device__ int      g_vmaxbits;

// ---------------- K Fuse0: kA1 (blocks 0..3839) + zero pmask + w1 stats + w2 transpose ----------------
__global__ void kFuse0(const int* __restrict__ inp,
                       const float* __restrict__ w1, const float* __restrict__ w2) {
    __shared__ uint8_t scs[264];
    __shared__ float smn[F1], smx[F1];
    int b = blockIdx.x, tid = threadIdx.x;

    if (b < 3840) {
        // ---- original kA1 body: channel sums -> horizontal 5-sums + packed bits ----
        int t = b >> 8, py = b & 255;
        int px = tid;
        int iy = py - 2, ix = px - 2;
        bool inr = (iy >= 0 && iy < H1 && ix >= 0 && ix < H1);
        int sum = 0;
        int bits[C1];
#pragma unroll
        for (int c = 0; c < C1; c++) {
            int v = inr ? inp[(((t * C1 + c) * H1) + iy) * H1 + ix] : 0;
            bits[c] = v; sum += v;
        }
        scs[px] = (uint8_t)sum;
        if (px < 8) scs[256 + px] = 0;
#pragma unroll
        for (int c = 0; c < C1; c++) {
            unsigned m = __ballot_sync(0xFFFFFFFFu, bits[c]);
            if ((px & 31) == 0)
                g_bits[((t * C1 + c) * HPADIN + py) * 8 + (px >> 5)] = m;
        }
        __syncthreads();
        int hs = scs[px] + scs[px + 1] + scs[px + 2] + scs[px + 3] + scs[px + 4];
        g_hs[(t * HPADIN + py) * HPADIN + px] = (uint8_t)hs;
        return;
    }

    int bb = b - 3840;
    if (bb < 240) {                                  // 240*256 int4 = sizeof(g_pmask)/16
        int i = bb * 256 + tid;
        ((int4*)g_pmask)[i] = make_int4(0, 0, 0, 0);
        if (i == 0) { g_count = 0; g_vmaxbits = 0; }
        return;
    }
    if (bb == 240) {
        if (tid < F1) {
            float mn = 1e30f, mx = -1e30f;
            for (int i = 0; i < 150; i++) {
                float w = w1[tid * 150 + i];
                mn = fminf(mn, w); mx = fmaxf(mx, w);
            }
            g_minwf[tid] = mn; g_maxwf[tid] = mx;
            smn[tid] = mn; smx[tid] = mx;
        }
        __syncthreads();
        if (tid == 0) {
            float mn = 1e30f, mx = -1e30f;
            for (int i = 0; i < F1; i++) { mn = fminf(mn, smn[i]); mx = fmaxf(mx, smx[i]); }
            g_minwA = mn; g_maxwA = mx; g_allpos = (mn > 0.f) ? 1 : 0;
        }
        return;
    }
    int tap = bb - 241;                              // 0..269
    g_w2t[tap * 256 + tid] = (tid < F2) ? w2[tid * TAPS + tap] : 0.0f;
}

// ---------------- K Prep2: S[f] (coalesced from g_w2t) + interior argmax ----------------
__global__ void kPrep2() {
    __shared__ float rv[256];
    __shared__ int   ri[256];
    int f = threadIdx.x;
    float s = 0.f;
#pragma unroll 5
    for (int t = 0; t < TAPS; t++) s += g_w2t[t * 256 + f];
    g_S[f] = (f < F2) ? s : 0.f;
    float sf = (f < F2 && s > 10.f) ? s : 0.f;
    rv[f] = sf; ri[f] = f;
    __syncthreads();
    for (int st = 128; st >= 1; st >>= 1) {
        if (f < st) {
            float o = rv[f + st]; int oi = ri[f + st];
            if (o > rv[f] || (o == rv[f] && oi < ri[f])) { rv[f] = o; ri[f] = oi; }
        }
        __syncthreads();
    }
    if (f == 0) { g_iMaxv = rv[0]; g_iMaxi = ri[0]; }
}

// ---------------- K A2: conv1 fire + maxpool -> spike bitmask ----------------
__global__ void __launch_bounds__(128) kA2(const float* __restrict__ w1) {
    __shared__ uint8_t  shs[12][68];
    __shared__ uint32_t sb[C1][12][4];
    __shared__ float    sminf[F1], smaxf[F1];
    int t = blockIdx.z;
    int px0 = blockIdx.x * 32, py0 = blockIdx.y * 4;
    int cx0 = px0 * 2, cy0 = py0 * 2;
    int tid = threadIdx.y * 32 + threadIdx.x;

    for (int i = tid; i < 12 * 68; i += 128) {
        int r = i / 68, cc = i % 68;
        int gr = cy0 + r, gc = cx0 + cc;
        uint8_t v = 0;
        if (gr < HPADIN && gc < HPADIN && cc < 65) v = g_hs[(t * HPADIN + gr) * HPADIN + gc];
        shs[r][cc] = v;
    }
    int wb = cx0 >> 5;
    for (int i = tid; i < C1 * 12 * 4; i += 128) {
        int c = i / 48, r = (i / 4) % 12, w = i & 3;
        int gr = cy0 + r, gw = wb + w;
        uint32_t v = 0;
        if (gr < HPADIN && gw < 8) v = g_bits[((t * C1 + c) * HPADIN + gr) * 8 + gw];
        sb[c][r][w] = v;
    }
    if (tid < F1) { sminf[tid] = g_minwf[tid]; smaxf[tid] = g_maxwf[tid]; }
    __syncthreads();

    int px = px0 + threadIdx.x, py = py0 + threadIdx.y;
    if (px >= HP || py >= HP) return;
    int lr = 2 * threadIdx.y, lc = 2 * threadIdx.x;

    int a0 = shs[lr + 0][lc], a1 = shs[lr + 1][lc], a2 = shs[lr + 2][lc];
    int a3 = shs[lr + 3][lc], a4 = shs[lr + 4][lc], a5 = shs[lr + 5][lc];
    int b0 = shs[lr + 0][lc + 1], b1 = shs[lr + 1][lc + 1], b2 = shs[lr + 2][lc + 1];
    int b3 = shs[lr + 3][lc + 1], b4 = shs[lr + 4][lc + 1], b5 = shs[lr + 5][lc + 1];
    int cnt[2][2];
    int am = a1 + a2 + a3 + a4, bm = b1 + b2 + b3 + b4;
    cnt[0][0] = a0 + am; cnt[1][0] = am + a5;
    cnt[0][1] = b0 + bm; cnt[1][1] = bm + b5;
    int maxcnt = max(max(cnt[0][0], cnt[0][1]), max(cnt[1][0], cnt[1][1]));

    bool ap = (g_allpos != 0);
    uint32_t* pm = &g_pmask[(t * HPD + py + 1) * HPD + (px + 1)];

    if (ap && g_minwA * maxcnt > 15.001f) { *pm = FULLMASK; return; }
    if (ap && g_maxwA * maxcnt < 14.999f) { *pm = 0u; return; }

    uint32_t mask = 0;
    for (int f = 0; f < F1; f++) {
        float mn = sminf[f], mx = smaxf[f];
        int pooled;
        if (ap && mn * maxcnt > 15.001f) pooled = 1;
        else if (ap && mx * maxcnt < 14.999f) pooled = 0;
        else {
            pooled = 0;
            for (int dy = 0; dy < 2 && !pooled; dy++)
                for (int dx = 0; dx < 2 && !pooled; dx++) {
                    float pot = 0.f;
                    int off = lc + dx;
                    int w = off >> 5, s = off & 31;
                    for (int ch = 0; ch < C1; ch++) {
#pragma unroll
                        for (int i = 0; i < 5; i++) {
                            uint32_t lo = sb[ch][lr + dy + i][w];
                            uint32_t hi = sb[ch][lr + dy + i][w + 1];
                            uint32_t ck = __funnelshift_r(lo, hi, s);
                            const float* wp = &w1[((f * C1 + ch) * 5 + i) * 5];
#pragma unroll
                            for (int j = 0; j < 5; j++)
                                if ((ck >> j) & 1) pot += __ldg(wp + j);
                        }
                    }
                    pooled = (pot > 15.f) ? 1 : 0;
                }
        }
        mask |= ((uint32_t)pooled) << f;
    }
    *pm = mask;
}

// ---------------- K B1: classify (t,pixel) full vs deficient ----------------
__global__ void kB1() {
    int i = blockIdx.x * 256 + threadIdx.x;
    if (i >= TT * NPIX) return;
    int t = i / NPIX, pix = i % NPIX;
    int y = pix / HP, x = pix % HP;
    int s = 0;
#pragma unroll
    for (int dy = 0; dy < 3; dy++) {
        const uint32_t* row = &g_pmask[(t * HPD + y + dy) * HPD + x];
        s += __popc(row[0]) + __popc(row[1]) + __popc(row[2]);
    }
    if (s == TAPS) {
        g_maxv[i] = g_iMaxv; g_maxi[i] = g_iMaxi;
    } else {
        int slot = atomicAdd(&g_count, 1);
        g_list[slot] = i;
    }
}

// ---------------- K B2: deficient (t,pixel): all-250 pot + first-argmax ----------------
__global__ void __launch_bounds__(256) kB2() {
    __shared__ uint32_t pmask[9];
    __shared__ float rv[256];
    __shared__ int   ri[256];
    int cnt = g_count;
    int f = threadIdx.x;
    for (int e = blockIdx.x; e < cnt; e += gridDim.x) {
        int id = g_list[e];
        int t = id / NPIX, pix = id % NPIX;
        int y = pix / HP, x = pix % HP;
        if (f < 9)
            pmask[f] = g_pmask[(t * HPD + y + f / 3) * HPD + x + f % 3];
        __syncthreads();
        float pot = g_S[f];
#pragma unroll
        for (int p = 0; p < 9; p++) {
            uint32_t mm = (~pmask[p]) & FULLMASK;
            while (mm) {
                int c = __ffs(mm) - 1; mm &= mm - 1;
                pot -= g_w2t[(c * 9 + p) * 256 + f];
            }
        }
        float pf = (f < F2 && pot > 10.f) ? pot : 0.f;
        rv[f] = pf; ri[f] = f;
        __syncthreads();
        for (int st = 128; st >= 1; st >>= 1) {
            if (f < st) {
                float o = rv[f + st]; int oi = ri[f + st];
                if (o > rv[f] || (o == rv[f] && oi < ri[f])) { rv[f] = o; ri[f] = oi; }
            }
            __syncthreads();
        }
        if (f == 0) { g_maxv[id] = rv[0]; g_maxi[id] = ri[0]; }
        __syncthreads();
    }
}

// ---------------- K B3: per-pixel earliest / winner feature / fired_last ----------------
__global__ void kB3() {
    int pix = blockIdx.x * 256 + threadIdx.x;
    if (pix >= NPIX) return;
    int cntf = 0, lastc = 0;
#pragma unroll
    for (int t = 0; t < TT; t++) {
        int c = (g_maxv[t * NPIX + pix] > 0.f) ? 1 : 0;
        cntf += c;
        if (t == TT - 1) lastc = c;
    }
    int e = TT - cntf; e = e < 0 ? 0 : (e > TT - 1 ? TT - 1 : e);
    g_win[pix] = g_maxi[e * NPIX + pix];
    g_fired[pix] = (uint8_t)lastc;
}

// ---------------- K B4: pot value of winning channel per (t,pixel) ----------------
__global__ void kB4() {
    int i = blockIdx.x * 256 + threadIdx.x;
    if (i >= TT * NPIX) return;
    int t = i / NPIX, pix = i % NPIX;
    float pv = 0.f;
    if (g_fired[pix]) {
        int win = g_win[pix];
        int y = pix / HP, x = pix % HP;
        uint32_t m[9];
        int s = 0;
#pragma unroll
        for (int p = 0; p < 9; p++) {
            m[p] = g_pmask[(t * HPD + y + p / 3) * HPD + x + p % 3];
            s += __popc(m[p]);
        }
        float pot = g_S[win];
        if (s != TAPS) {
#pragma unroll
            for (int p = 0; p < 9; p++) {            // (p outer, c ascending) == kB2 order
                uint32_t mm = (~m[p]) & FULLMASK;
                while (mm) {
                    int c = __ffs(mm) - 1; mm &= mm - 1;
                    pot -= g_w2t[(c * 9 + p) * 256 + win];
                }
            }
        }
        pv = (pot > 10.f) ? pot : 0.f;
    }
    g_pv[i] = pv;
}

// ---------------- K W: fused zero-fill + winner scatter (writes all 476 MB once) ----------------
__global__ void __launch_bounds__(256) kWrite(float* __restrict__ out) {
    unsigned idx4 = blockIdx.x * 256u + threadIdx.x;   // int4 index
    if (idx4 >= NQUAD) return;
    unsigned plane = idx4 / 3969u;                     // t*250+f
    unsigned r = idx4 - plane * 3969u;
    unsigned pix = r * 4u;
    unsigned t = plane / F2;
    unsigned f = plane - t * F2;
    int4   w4 = *(const int4*)&g_win[pix];
    float4 p4 = *(const float4*)&g_pv[t * NPIX + pix];
    bool h0 = (w4.x == (int)f) && (p4.x > 0.f);
    bool h1 = (w4.y == (int)f) && (p4.y > 0.f);
    bool h2 = (w4.z == (int)f) && (p4.z > 0.f);
    bool h3 = (w4.w == (int)f) && (p4.w > 0.f);
    float4 sv = make_float4(h0 ? 1.f : 0.f, h1 ? 1.f : 0.f, h2 ? 1.f : 0.f, h3 ? 1.f : 0.f);
    float4 pvv = make_float4(h0 ? p4.x : 0.f, h1 ? p4.y : 0.f, h2 ? p4.z : 0.f, h3 ? p4.w : 0.f);
    size_t base = (size_t)idx4 * 4u;
    __stcs((float4*)(out + base), sv);
    __stcs((float4*)(out + POT_OFF + base), pvv);
}

// ---------------- K B5a: earliest firing value + global vmax ----------------
__global__ void kB5a() {
    int pix = blockIdx.x * 256 + threadIdx.x;
    if (pix >= NPIX) return;
    int ns = 0;
#pragma unroll
    for (int t = 0; t < TT; t++) ns += (g_pv[t * NPIX + pix] > 0.f) ? 1 : 0;
    int e = TT - ns; e = e < 0 ? 0 : (e > TT - 1 ? TT - 1 : e);
    float val = g_pv[e * NPIX + pix];
    g_val[pix] = val;
    if (ns > 0) atomicMax(&g_vmaxbits, __float_as_int(val));
}

// ---------------- K B5b: per-pixel totals ----------------
__global__ void kB5b() {
    int pix = blockIdx.x * 256 + threadIdx.x;
    if (pix >= NPIX) return;
    float v = __int_as_float(g_vmaxbits) * 15.0f;
    float w = g_val[pix] + v;
    float tot = 0.f;
#pragma unroll
    for (int t = 0; t < TT; t++)
        if (g_pv[t * NPIX + pix] > 0.f) tot += w;
    g_total[pix] = tot;
}

// ---------------- K B6: k-winners ----------------
__global__ void __launch_bounds__(1024) kB6(float* __restrict__ outw) {
    __shared__ unsigned long long red[1024];
    __shared__ int winfo[3];
    int tid = threadIdx.x;
    unsigned kill = 0;
    for (int r = 0; r < 8; r++) {
        unsigned long long best = 0;
        for (int k = 0; k < 16; k++) {
            int e = tid * 16 + k;
            if (e < NPIX && !((kill >> k) & 1u)) {
                float tv = g_total[e];
                if (tv > 0.f) {
                    unsigned flat = (unsigned)(g_win[e] * NPIX + e);
                    unsigned long long key =
                        ((unsigned long long)__float_as_uint(tv) << 32) | (0xFFFFFFFFu - flat);
                    if (key > best) best = key;
                }
            }
        }
        red[tid] = best;
        __syncthreads();
        for (int st = 512; st >= 1; st >>= 1) {
            if (tid < st) {
                unsigned long long o = red[tid + st];
                if (o > red[tid]) red[tid] = o;
            }
            __syncthreads();
        }
        if (tid == 0) {
            unsigned long long b = red[0];
            if (b == 0) {
                winfo[0] = -1;
                outw[r * 3] = -1.f; outw[r * 3 + 1] = -1.f; outw[r * 3 + 2] = -1.f;
            } else {
                unsigned flat = 0xFFFFFFFFu - (unsigned)(b & 0xFFFFFFFFu);
                int c = flat / NPIX, pix = flat % NPIX;
                winfo[0] = c; winfo[1] = pix / HP; winfo[2] = pix % HP;
                outw[r * 3] = (float)c;
                outw[r * 3 + 1] = (float)winfo[1];
                outw[r * 3 + 2] = (float)winfo[2];
            }
        }
        __syncthreads();
        int wc = winfo[0];
        if (wc >= 0) {
            int wy = winfo[1], wx = winfo[2];
            for (int k = 0; k < 16; k++) {
                int e = tid * 16 + k;
                if (e < NPIX) {
                    int y = e / HP, x = e % HP;
                    if (g_win[e] == wc || (abs(y - wy) <= 1 && abs(x - wx) <= 1))
                        kill |= (1u << k);
                }
            }
        }
        __syncthreads();
    }
}

// ---------------- host launcher (R6 topology: fork after kB4, writer || tail) ----------------
extern "C" void kernel_launch(void* const* d_in, const int* in_sizes, int n_in,
                              void* d_out, int out_size) {
    const int*   inp = (const int*)d_in[0];
    const float* w1  = (const float*)d_in[2];
    const float* w2  = (const float*)d_in[3];
    float* out = (float*)d_out;

    cudaStream_t s2;
    cudaEvent_t evFork, evJoin;
    cudaStreamCreateWithFlags(&s2, cudaStreamNonBlocking);
    cudaEventCreateWithFlags(&evFork, cudaEventDisableTiming);
    cudaEventCreateWithFlags(&evJoin, cudaEventDisableTiming);

    kFuse0<<<4351, 256>>>(inp, w1, w2);
    kPrep2<<<1, 256>>>();
    dim3 gA2(4, 32, TT), bA2(32, 4);
    kA2<<<gA2, bA2>>>(w1);
    kB1<<<(TT * NPIX + 255) / 256, 256>>>();
    kB2<<<4096, 256>>>();
    kB3<<<(NPIX + 255) / 256, 256>>>();
    kB4<<<(TT * NPIX + 255) / 256, 256>>>();

    // fork: side stream computes totals + k-winners while main streams the 476 MB write
    cudaEventRecord(evFork, 0);
    cudaStreamWaitEvent(s2, evFork, 0);
    kB5a<<<(NPIX + 255) / 256, 256, 0, s2>>>();
    kB5b<<<(NPIX + 255) / 256, 256, 0, s2>>>();
    kB6<<<1, 1024, 0, s2>>>(out + WIN_OFF);
    cudaEventRecord(evJoin, s2);

    kWrite<<<(NQUAD + 255) / 256, 256>>>(out);

    cudaStreamWaitEvent(0, evJoin, 0);

    cudaStreamDestroy(s2);
    cudaEventDestroy(evFork);
    cudaEventDestroy(evJoin);
}

// round 15
// speedup vs baseline: 1.2876x; 1.0016x over previous
#include <cuda_runtime.h>
#include <cuda_bf16.h>
#include <cstdint>

#define TT 15
#define C1 6
#define F1 30
#define H1 252
#define HPADIN 256
#define HP 126
#define HPD 128
#define F2 250
#define NPIX (HP*HP)          /* 15876 */
#define TAPS 270
#define POT_OFF 59535000u
#define WIN_OFF 119070000u
#define FULLMASK 0x3FFFFFFFu
#define NBYTES 476280000ull   /* bytes of the two big halves */
#define FILLB 1184

// ---------------- device scratch ----------------
__device__ uint8_t  g_hs[TT*HPADIN*HPADIN];          // horizontal 5-sums of channel sums
__device__ uint32_t g_bits[TT*C1*HPADIN*8];          // packed input bits (padded coords)
__device__ uint32_t g_pmask[TT*HPD*HPD];             // pooled+padded spike bitmask (bit c)
__device__ float    g_w2t[TAPS*256];
__device__ float    g_S[256];
__device__ float    g_minwf[F1], g_maxwf[F1];
__device__ float    g_minwA, g_maxwA;
__device__ int      g_allpos;
__device__ float    g_iMaxv;
__device__ int      g_iMaxi;
__device__ float    g_maxv[TT*NPIX];
__device__ int      g_maxi[TT*NPIX];
__device__ float    g_pv[TT*NPIX];
__device__ int      g_win[NPIX];
__device__ uint8_t  g_fired[NPIX];
__device__ float    g_val[NPIX];
__device__ float    g_total[NPIX];
__device__ int      g_list[TT*NPIX];
__device__ int      g_count;
__device__ int      g_vmaxbits;

// ---------------- K Fuse0: kA1 (blocks 0..3839) + zero pmask + w1 stats + w2 transpose ----------------
__global__ void kFuse0(const int* __restrict__ inp,
                       const float* __restrict__ w1, const float* __restrict__ w2) {
    __shared__ uint8_t scs[264];
    __shared__ float smn[F1], smx[F1];
    int b = blockIdx.x, tid = threadIdx.x;

    if (b < 3840) {
        int t = b >> 8, py = b & 255;
        int px = tid;
        int iy = py - 2, ix = px - 2;
        bool inr = (iy >= 0 && iy < H1 && ix >= 0 && ix < H1);
        int sum = 0;
        int bits[C1];
#pragma unroll
        for (int c = 0; c < C1; c++) {
            int v = inr ? inp[(((t * C1 + c) * H1) + iy) * H1 + ix] : 0;
            bits[c] = v; sum += v;
        }
        scs[px] = (uint8_t)sum;
        if (px < 8) scs[256 + px] = 0;
#pragma unroll
        for (int c = 0; c < C1; c++) {
            unsigned m = __ballot_sync(0xFFFFFFFFu, bits[c]);
            if ((px & 31) == 0)
                g_bits[((t * C1 + c) * HPADIN + py) * 8 + (px >> 5)] = m;
        }
        __syncthreads();
        int hs = scs[px] + scs[px + 1] + scs[px + 2] + scs[px + 3] + scs[px + 4];
        g_hs[(t * HPADIN + py) * HPADIN + px] = (uint8_t)hs;
        return;
    }

    int bb = b - 3840;
    if (bb < 240) {                                  // 240*256 int4 = sizeof(g_pmask)/16
        int i = bb * 256 + tid;
        ((int4*)g_pmask)[i] = make_int4(0, 0, 0, 0);
        if (i == 0) { g_count = 0; g_vmaxbits = 0; }
        return;
    }
    if (bb == 240) {
        if (tid < F1) {
            float mn = 1e30f, mx = -1e30f;
            for (int i = 0; i < 150; i++) {
                float w = w1[tid * 150 + i];
                mn = fminf(mn, w); mx = fmaxf(mx, w);
            }
            g_minwf[tid] = mn; g_maxwf[tid] = mx;
            smn[tid] = mn; smx[tid] = mx;
        }
        __syncthreads();
        if (tid == 0) {
            float mn = 1e30f, mx = -1e30f;
            for (int i = 0; i < F1; i++) { mn = fminf(mn, smn[i]); mx = fmaxf(mx, smx[i]); }
            g_minwA = mn; g_maxwA = mx; g_allpos = (mn > 0.f) ? 1 : 0;
        }
        return;
    }
    int tap = bb - 241;                              // 0..269
    g_w2t[tap * 256 + tid] = (tid < F2) ? w2[tid * TAPS + tap] : 0.0f;
}

// ---------------- K Prep2: S[f] (coalesced from g_w2t) + interior argmax ----------------
__global__ void kPrep2() {
    __shared__ float rv[256];
    __shared__ int   ri[256];
    int f = threadIdx.x;
    float s = 0.f;
#pragma unroll 5
    for (int t = 0; t < TAPS; t++) s += g_w2t[t * 256 + f];
    g_S[f] = (f < F2) ? s : 0.f;
    float sf = (f < F2 && s > 10.f) ? s : 0.f;
    rv[f] = sf; ri[f] = f;
    __syncthreads();
    for (int st = 128; st >= 1; st >>= 1) {
        if (f < st) {
            float o = rv[f + st]; int oi = ri[f + st];
            if (o > rv[f] || (o == rv[f] && oi < ri[f])) { rv[f] = o; ri[f] = oi; }
        }
        __syncthreads();
    }
    if (f == 0) { g_iMaxv = rv[0]; g_iMaxi = ri[0]; }
}

// ---------------- K A2: conv1 fire + maxpool -> spike bitmask ----------------
__global__ void __launch_bounds__(128) kA2(const float* __restrict__ w1) {
    __shared__ uint8_t  shs[12][68];
    __shared__ uint32_t sb[C1][12][4];
    __shared__ float    sminf[F1], smaxf[F1];
    int t = blockIdx.z;
    int px0 = blockIdx.x * 32, py0 = blockIdx.y * 4;
    int cx0 = px0 * 2, cy0 = py0 * 2;
    int tid = threadIdx.y * 32 + threadIdx.x;

    for (int i = tid; i < 12 * 68; i += 128) {
        int r = i / 68, cc = i % 68;
        int gr = cy0 + r, gc = cx0 + cc;
        uint8_t v = 0;
        if (gr < HPADIN && gc < HPADIN && cc < 65) v = g_hs[(t * HPADIN + gr) * HPADIN + gc];
        shs[r][cc] = v;
    }
    int wb = cx0 >> 5;
    for (int i = tid; i < C1 * 12 * 4; i += 128) {
        int c = i / 48, r = (i / 4) % 12, w = i & 3;
        int gr = cy0 + r, gw = wb + w;
        uint32_t v = 0;
        if (gr < HPADIN && gw < 8) v = g_bits[((t * C1 + c) * HPADIN + gr) * 8 + gw];
        sb[c][r][w] = v;
    }
    if (tid < F1) { sminf[tid] = g_minwf[tid]; smaxf[tid] = g_maxwf[tid]; }
    __syncthreads();

    int px = px0 + threadIdx.x, py = py0 + threadIdx.y;
    if (px >= HP || py >= HP) return;
    int lr = 2 * threadIdx.y, lc = 2 * threadIdx.x;

    int a0 = shs[lr + 0][lc], a1 = shs[lr + 1][lc], a2 = shs[lr + 2][lc];
    int a3 = shs[lr + 3][lc], a4 = shs[lr + 4][lc], a5 = shs[lr + 5][lc];
    int b0 = shs[lr + 0][lc + 1], b1 = shs[lr + 1][lc + 1], b2 = shs[lr + 2][lc + 1];
    int b3 = shs[lr + 3][lc + 1], b4 = shs[lr + 4][lc + 1], b5 = shs[lr + 5][lc + 1];
    int cnt[2][2];
    int am = a1 + a2 + a3 + a4, bm = b1 + b2 + b3 + b4;
    cnt[0][0] = a0 + am; cnt[1][0] = am + a5;
    cnt[0][1] = b0 + bm; cnt[1][1] = bm + b5;
    int maxcnt = max(max(cnt[0][0], cnt[0][1]), max(cnt[1][0], cnt[1][1]));

    bool ap = (g_allpos != 0);
    uint32_t* pm = &g_pmask[(t * HPD + py + 1) * HPD + (px + 1)];

    if (ap && g_minwA * maxcnt > 15.001f) { *pm = FULLMASK; return; }
    if (ap && g_maxwA * maxcnt < 14.999f) { *pm = 0u; return; }

    uint32_t mask = 0;
    for (int f = 0; f < F1; f++) {
        float mn = sminf[f], mx = smaxf[f];
        int pooled;
        if (ap && mn * maxcnt > 15.001f) pooled = 1;
        else if (ap && mx * maxcnt < 14.999f) pooled = 0;
        else {
            pooled = 0;
            for (int dy = 0; dy < 2 && !pooled; dy++)
                for (int dx = 0; dx < 2 && !pooled; dx++) {
                    float pot = 0.f;
                    int off = lc + dx;
                    int w = off >> 5, s = off & 31;
                    for (int ch = 0; ch < C1; ch++) {
#pragma unroll
                        for (int i = 0; i < 5; i++) {
                            uint32_t lo = sb[ch][lr + dy + i][w];
                            uint32_t hi = sb[ch][lr + dy + i][w + 1];
                            uint32_t ck = __funnelshift_r(lo, hi, s);
                            const float* wp = &w1[((f * C1 + ch) * 5 + i) * 5];
#pragma unroll
                            for (int j = 0; j < 5; j++)
                                if ((ck >> j) & 1) pot += __ldg(wp + j);
                        }
                    }
                    pooled = (pot > 15.f) ? 1 : 0;
                }
        }
        mask |= ((uint32_t)pooled) << f;
    }
    *pm = mask;
}

// ---------------- K B1: classify (t,pixel) full vs deficient ----------------
__global__ void kB1() {
    int i = blockIdx.x * 256 + threadIdx.x;
    if (i >= TT * NPIX) return;
    int t = i / NPIX, pix = i % NPIX;
    int y = pix / HP, x = pix % HP;
    int s = 0;
#pragma unroll
    for (int dy = 0; dy < 3; dy++) {
        const uint32_t* row = &g_pmask[(t * HPD + y + dy) * HPD + x];
        s += __popc(row[0]) + __popc(row[1]) + __popc(row[2]);
    }
    if (s == TAPS) {
        g_maxv[i] = g_iMaxv; g_maxi[i] = g_iMaxi;
    } else {
        int slot = atomicAdd(&g_count, 1);
        g_list[slot] = i;
    }
}

// ---------------- K B2: deficient (t,pixel): all-250 pot + first-argmax ----------------
__global__ void __launch_bounds__(256) kB2() {
    __shared__ uint32_t pmask[9];
    __shared__ float rv[256];
    __shared__ int   ri[256];
    int cnt = g_count;
    int f = threadIdx.x;
    for (int e = blockIdx.x; e < cnt; e += gridDim.x) {
        int id = g_list[e];
        int t = id / NPIX, pix = id % NPIX;
        int y = pix / HP, x = pix % HP;
        if (f < 9)
            pmask[f] = g_pmask[(t * HPD + y + f / 3) * HPD + x + f % 3];
        __syncthreads();
        float pot = g_S[f];
#pragma unroll
        for (int p = 0; p < 9; p++) {
            uint32_t mm = (~pmask[p]) & FULLMASK;
            while (mm) {
                int c = __ffs(mm) - 1; mm &= mm - 1;
                pot -= g_w2t[(c * 9 + p) * 256 + f];
            }
        }
        float pf = (f < F2 && pot > 10.f) ? pot : 0.f;
        rv[f] = pf; ri[f] = f;
        __syncthreads();
        for (int st = 128; st >= 1; st >>= 1) {
            if (f < st) {
                float o = rv[f + st]; int oi = ri[f + st];
                if (o > rv[f] || (o == rv[f] && oi < ri[f])) { rv[f] = o; ri[f] = oi; }
            }
            __syncthreads();
        }
        if (f == 0) { g_maxv[id] = rv[0]; g_maxi[id] = ri[0]; }
        __syncthreads();
    }
}

// ---------------- K B3: per-pixel earliest / winner feature / fired_last ----------------
__global__ void kB3() {
    int pix = blockIdx.x * 256 + threadIdx.x;
    if (pix >= NPIX) return;
    int cntf = 0, lastc = 0;
#pragma unroll
    for (int t = 0; t < TT; t++) {
        int c = (g_maxv[t * NPIX + pix] > 0.f) ? 1 : 0;
        cntf += c;
        if (t == TT - 1) lastc = c;
    }
    int e = TT - cntf; e = e < 0 ? 0 : (e > TT - 1 ? TT - 1 : e);
    g_win[pix] = g_maxi[e * NPIX + pix];
    g_fired[pix] = (uint8_t)lastc;
}

// ---------------- K B4: pot value of winning channel per (t,pixel) ----------------
__global__ void kB4() {
    int i = blockIdx.x * 256 + threadIdx.x;
    if (i >= TT * NPIX) return;
    int t = i / NPIX, pix = i % NPIX;
    float pv = 0.f;
    if (g_fired[pix]) {
        int win = g_win[pix];
        int y = pix / HP, x = pix % HP;
        uint32_t m[9];
        int s = 0;
#pragma unroll
        for (int p = 0; p < 9; p++) {
            m[p] = g_pmask[(t * HPD + y + p / 3) * HPD + x + p % 3];
            s += __popc(m[p]);
        }
        float pot = g_S[win];
        if (s != TAPS) {
#pragma unroll
            for (int p = 0; p < 9; p++) {            // (p outer, c ascending) == kB2 order
                uint32_t mm = (~m[p]) & FULLMASK;
                while (mm) {
                    int c = __ffs(mm) - 1; mm &= mm - 1;
                    pot -= g_w2t[(c * 9 + p) * 256 + win];
                }
            }
        }
        pv = (pot > 10.f) ? pot : 0.f;
    }
    g_pv[i] = pv;
}

// ---------------- K FillTMA: bulk-copy zeros SMEM->GMEM (one instr per 32KB) ----------------
__global__ void __launch_bounds__(256) kFillTMA(float* __restrict__ out) {
    __shared__ __align__(16) uint8_t zbuf[32768];
    for (int i = threadIdx.x; i < 32768 / 16; i += 256)
        ((int4*)zbuf)[i] = make_int4(0, 0, 0, 0);
    __syncthreads();
    if (threadIdx.x == 0) {
        asm volatile("fence.proxy.async.shared::cta;" ::: "memory");
        const unsigned long long per = ((NBYTES / FILLB + 15ull) & ~15ull);   // 402272, mult of 16
        unsigned long long begin = (unsigned long long)blockIdx.x * per;
        unsigned long long end = begin + per; if (end > NBYTES) end = NBYTES;
        uint32_t saddr = (uint32_t)__cvta_generic_to_shared(zbuf);
        unsigned char* dst = (unsigned char*)out + begin;
        while (begin < end) {
            unsigned sz = (unsigned)(end - begin > 32768ull ? 32768ull : end - begin);
            asm volatile("cp.async.bulk.global.shared::cta.bulk_group [%0], [%1], %2;"
                         :: "l"(dst), "r"(saddr), "r"(sz) : "memory");
            dst += sz; begin += sz;
        }
        asm volatile("cp.async.bulk.commit_group;" ::: "memory");
        asm volatile("cp.async.bulk.wait_group 0;" ::: "memory");
    }
}

// ---------------- K Scatter: sparse winner writes into zero-filled output ----------------
__global__ void kScatter(float* __restrict__ out) {
    int i = blockIdx.x * 256 + threadIdx.x;
    if (i >= TT * NPIX) return;
    int t = i / NPIX, pix = i % NPIX;
    float pv = g_pv[i];
    if (pv > 0.f) {
        int win = g_win[pix];
        size_t idx = ((size_t)(t * F2 + win)) * NPIX + pix;
        out[idx] = 1.0f;
        out[POT_OFF + idx] = pv;
    }
}

// ---------------- K B5a: earliest firing value + global vmax ----------------
__global__ void kB5a() {
    int pix = blockIdx.x * 256 + threadIdx.x;
    if (pix >= NPIX) return;
    int ns = 0;
#pragma unroll
    for (int t = 0; t < TT; t++) ns += (g_pv[t * NPIX + pix] > 0.f) ? 1 : 0;
    int e = TT - ns; e = e < 0 ? 0 : (e > TT - 1 ? TT - 1 : e);
    float val = g_pv[e * NPIX + pix];
    g_val[pix] = val;
    if (ns > 0) atomicMax(&g_vmaxbits, __float_as_int(val));
}

// ---------------- K B5b: per-pixel totals ----------------
__global__ void kB5b() {
    int pix = blockIdx.x * 256 + threadIdx.x;
    if (pix >= NPIX) return;
    float v = __int_as_float(g_vmaxbits) * 15.0f;
    float w = g_val[pix] + v;
    float tot = 0.f;
#pragma unroll
    for (int t = 0; t < TT; t++)
        if (g_pv[t * NPIX + pix] > 0.f) tot += w;
    g_total[pix] = tot;
}

// ---------------- K B6: k-winners ----------------
__global__ void __launch_bounds__(1024) kB6(float* __restrict__ outw) {
    __shared__ unsigned long long red[1024];
    __shared__ int winfo[3];
    int tid = threadIdx.x;
    unsigned kill = 0;
    for (int r = 0; r < 8; r++) {
        unsigned long long best = 0;
        for (int k = 0; k < 16; k++) {
            int e = tid * 16 + k;
            if (e < NPIX && !((kill >> k) & 1u)) {
                float tv = g_total[e];
                if (tv > 0.f) {
                    unsigned flat = (unsigned)(g_win[e] * NPIX + e);
                    unsigned long long key =
                        ((unsigned long long)__float_as_uint(tv) << 32) | (0xFFFFFFFFu - flat);
                    if (key > best) best = key;
                }
            }
        }
        red[tid] = best;
        __syncthreads();
        for (int st = 512; st >= 1; st >>= 1) {
            if (tid < st) {
                unsigned long long o = red[tid + st];
                if (o > red[tid]) red[tid] = o;
            }
            __syncthreads();
        }
        if (tid == 0) {
            unsigned long long b = red[0];
            if (b == 0) {
                winfo[0] = -1;
                outw[r * 3] = -1.f; outw[r * 3 + 1] = -1.f; outw[r * 3 + 2] = -1.f;
            } else {
                unsigned flat = 0xFFFFFFFFu - (unsigned)(b & 0xFFFFFFFFu);
                int c = flat / NPIX, pix = flat % NPIX;
                winfo[0] = c; winfo[1] = pix / HP; winfo[2] = pix % HP;
                outw[r * 3] = (float)c;
                outw[r * 3 + 1] = (float)winfo[1];
                outw[r * 3 + 2] = (float)winfo[2];
            }
        }
        __syncthreads();
        int wc = winfo[0];
        if (wc >= 0) {
            int wy = winfo[1], wx = winfo[2];
            for (int k = 0; k < 16; k++) {
                int e = tid * 16 + k;
                if (e < NPIX) {
                    int y = e / HP, x = e % HP;
                    if (g_win[e] == wc || (abs(y - wy) <= 1 && abs(x - wx) <= 1))
                        kill |= (1u << k);
                }
            }
        }
        __syncthreads();
    }
}

// ---------------- host launcher (R14 topology; kWrite -> kFillTMA + kScatter) ----------------
extern "C" void kernel_launch(void* const* d_in, const int* in_sizes, int n_in,
                              void* d_out, int out_size) {
    const int*   inp = (const int*)d_in[0];
    const float* w1  = (const float*)d_in[2];
    const float* w2  = (const float*)d_in[3];
    float* out = (float*)d_out;

    cudaStream_t s2;
    cudaEvent_t evFork, evJoin;
    cudaStreamCreateWithFlags(&s2, cudaStreamNonBlocking);
    cudaEventCreateWithFlags(&evFork, cudaEventDisableTiming);
    cudaEventCreateWithFlags(&evJoin, cudaEventDisableTiming);

    kFuse0<<<4351, 256>>>(inp, w1, w2);
    kPrep2<<<1, 256>>>();
    dim3 gA2(4, 32, TT), bA2(32, 4);
    kA2<<<gA2, bA2>>>(w1);
    kB1<<<(TT * NPIX + 255) / 256, 256>>>();
    kB2<<<4096, 256>>>();
    kB3<<<(NPIX + 255) / 256, 256>>>();
    kB4<<<(TT * NPIX + 255) / 256, 256>>>();

    // fork: side stream computes totals + k-winners while main fills the 476 MB
    cudaEventRecord(evFork, 0);
    cudaStreamWaitEvent(s2, evFork, 0);
    kB5a<<<(NPIX + 255) / 256, 256, 0, s2>>>();
    kB5b<<<(NPIX + 255) / 256, 256, 0, s2>>>();
    kB6<<<1, 1024, 0, s2>>>(out + WIN_OFF);
    cudaEventRecord(evJoin, s2);

    kFillTMA<<<FILLB, 256>>>(out);
    kScatter<<<(TT * NPIX + 255) / 256, 256>>>(out);

    cudaStreamWaitEvent(0, evJoin, 0);

    cudaStreamDestroy(s2);
    cudaEventDestroy(evFork);
    cudaEventDestroy(evJoin);
}

// round 16
// speedup vs baseline: 1.2933x; 1.0044x over previous
#include <cuda_runtime.h>
#include <cuda_bf16.h>
#include <cstdint>

#define TT 15
#define C1 6
#define F1 30
#define H1 252
#define HPADIN 256
#define HP 126
#define HPD 128
#define F2 250
#define NPIX (HP*HP)          /* 15876 */
#define TAPS 270
#define POT_OFF 59535000u
#define WIN_OFF 119070000u
#define FULLMASK 0x3FFFFFFFu
#define NQ2 29767500u         /* float4 count of the two big halves */

/* fill-chunk layout (float4 units, 4096 per block) */
#define F0_FILLB  384u
#define A2_FILLZ  3
#define A2_FILLB  (A2_FILLZ*128u)
#define B1_FILLB  256u
#define B2_FILLB  512u
#define B3_FILLB  128u
#define B4_FILLB  384u
#define F0_BEGIN  0u
#define A2_BEGIN  (F0_BEGIN + F0_FILLB*4096u)        /* 1572864 */
#define B1_BEGIN  (A2_BEGIN + A2_FILLB*4096u)        /* 3145728 */
#define B2_BEGIN  (B1_BEGIN + B1_FILLB*4096u)        /* 4194304 */
#define B3_BEGIN  (B2_BEGIN + B2_FILLB*4096u)        /* 6291456 */
#define B4_BEGIN  (B3_BEGIN + B3_FILLB*4096u)        /* 6815744 */
#define REST_BEGIN (B4_BEGIN + B4_FILLB*4096u)       /* 8388608 */

// ---------------- device scratch ----------------
__device__ uint8_t  g_hs[TT*HPADIN*HPADIN];
__device__ uint32_t g_bits[TT*C1*HPADIN*8];
__device__ uint32_t g_pmask[TT*HPD*HPD];
__device__ float    g_w2t[TAPS*256];
__device__ float    g_S[256];
__device__ float    g_minwf[F1], g_maxwf[F1];
__device__ float    g_minwA, g_maxwA;
__device__ int      g_allpos;
__device__ float    g_iMaxv;
__device__ int      g_iMaxi;
__device__ float    g_maxv[TT*NPIX];
__device__ int      g_maxi[TT*NPIX];
__device__ float    g_pv[TT*NPIX];
__device__ int      g_win[NPIX];
__device__ uint8_t  g_fired[NPIX];
__device__ float    g_val[NPIX];
__device__ float    g_total[NPIX];
__device__ int      g_list[TT*NPIX];
__device__ int      g_count;
__device__ int      g_vmaxbits;

// ---------------- fill helper: one block zeroes 4096 float4 (64 KB), guaranteed in-range ----------------
__device__ __forceinline__ void fillBlk(float* __restrict__ out, unsigned blk, unsigned begin4) {
    float4* o = (float4*)out + begin4 + blk * 4096u + threadIdx.x;
    const float4 z = make_float4(0.f, 0.f, 0.f, 0.f);
#pragma unroll
    for (int k = 0; k < 16; k++)
        __stcs(o + k * 256, z);
}

// ---------------- K Fuse0: kA1 (blocks 0..3839) + zero pmask + w1 stats + w2 transpose + fill ----------------
__global__ void kFuse0(const int* __restrict__ inp,
                       const float* __restrict__ w1, const float* __restrict__ w2,
                       float* __restrict__ out) {
    __shared__ uint8_t scs[264];
    __shared__ float smn[F1], smx[F1];
    int b = blockIdx.x, tid = threadIdx.x;

    if (b < 3840) {
        int t = b >> 8, py = b & 255;
        int px = tid;
        int iy = py - 2, ix = px - 2;
        bool inr = (iy >= 0 && iy < H1 && ix >= 0 && ix < H1);
        int sum = 0;
        int bits[C1];
#pragma unroll
        for (int c = 0; c < C1; c++) {
            int v = inr ? inp[(((t * C1 + c) * H1) + iy) * H1 + ix] : 0;
            bits[c] = v; sum += v;
        }
        scs[px] = (uint8_t)sum;
        if (px < 8) scs[256 + px] = 0;
#pragma unroll
        for (int c = 0; c < C1; c++) {
            unsigned m = __ballot_sync(0xFFFFFFFFu, bits[c]);
            if ((px & 31) == 0)
                g_bits[((t * C1 + c) * HPADIN + py) * 8 + (px >> 5)] = m;
        }
        __syncthreads();
        int hs = scs[px] + scs[px + 1] + scs[px + 2] + scs[px + 3] + scs[px + 4];
        g_hs[(t * HPADIN + py) * HPADIN + px] = (uint8_t)hs;
        return;
    }

    int bb = b - 3840;
    if (bb < 240) {                                  // 240*256 int4 = sizeof(g_pmask)/16
        int i = bb * 256 + tid;
        ((int4*)g_pmask)[i] = make_int4(0, 0, 0, 0);
        if (i == 0) { g_count = 0; g_vmaxbits = 0; }
        return;
    }
    if (bb == 240) {
        if (tid < F1) {
            float mn = 1e30f, mx = -1e30f;
            for (int i = 0; i < 150; i++) {
                float w = w1[tid * 150 + i];
                mn = fminf(mn, w); mx = fmaxf(mx, w);
            }
            g_minwf[tid] = mn; g_maxwf[tid] = mx;
            smn[tid] = mn; smx[tid] = mx;
        }
        __syncthreads();
        if (tid == 0) {
            float mn = 1e30f, mx = -1e30f;
            for (int i = 0; i < F1; i++) { mn = fminf(mn, smn[i]); mx = fmaxf(mx, smx[i]); }
            g_minwA = mn; g_maxwA = mx; g_allpos = (mn > 0.f) ? 1 : 0;
        }
        return;
    }
    if (bb < 241 + TAPS) {
        int tap = bb - 241;                          // 0..269
        g_w2t[tap * 256 + tid] = (tid < F2) ? w2[tid * TAPS + tap] : 0.0f;
        return;
    }
    fillBlk(out, (unsigned)(bb - 241 - TAPS), F0_BEGIN);
}

// ---------------- K Prep2: S[f] (coalesced from g_w2t) + interior argmax ----------------
__global__ void kPrep2() {
    __shared__ float rv[256];
    __shared__ int   ri[256];
    int f = threadIdx.x;
    float s = 0.f;
#pragma unroll 5
    for (int t = 0; t < TAPS; t++) s += g_w2t[t * 256 + f];
    g_S[f] = (f < F2) ? s : 0.f;
    float sf = (f < F2 && s > 10.f) ? s : 0.f;
    rv[f] = sf; ri[f] = f;
    __syncthreads();
    for (int st = 128; st >= 1; st >>= 1) {
        if (f < st) {
            float o = rv[f + st]; int oi = ri[f + st];
            if (o > rv[f] || (o == rv[f] && oi < ri[f])) { rv[f] = o; ri[f] = oi; }
        }
        __syncthreads();
    }
    if (f == 0) { g_iMaxv = rv[0]; g_iMaxi = ri[0]; }
}

// ---------------- K A2: conv1 fire + maxpool -> spike bitmask (+fill z-slices) ----------------
__global__ void __launch_bounds__(128) kA2(const float* __restrict__ w1, float* __restrict__ out) {
    __shared__ uint8_t  shs[12][68];
    __shared__ uint32_t sb[C1][12][4];
    __shared__ float    sminf[F1], smaxf[F1];
    int t = blockIdx.z;
    int tid = threadIdx.y * 32 + threadIdx.x;

    if (t >= TT) {
        // fill slice: 128 blocks per z, each 2048 float4 with 128 threads x 16 iters
        unsigned blk = (unsigned)(t - TT) * 128u + blockIdx.y * 4u + blockIdx.x;
        float4* o = (float4*)out + A2_BEGIN + blk * 4096u + tid;
        const float4 z = make_float4(0.f, 0.f, 0.f, 0.f);
#pragma unroll
        for (int k = 0; k < 32; k++)
            __stcs(o + k * 128, z);
        return;
    }

    int px0 = blockIdx.x * 32, py0 = blockIdx.y * 4;
    int cx0 = px0 * 2, cy0 = py0 * 2;

    for (int i = tid; i < 12 * 68; i += 128) {
        int r = i / 68, cc = i % 68;
        int gr = cy0 + r, gc = cx0 + cc;
        uint8_t v = 0;
        if (gr < HPADIN && gc < HPADIN && cc < 65) v = g_hs[(t * HPADIN + gr) * HPADIN + gc];
        shs[r][cc] = v;
    }
    int wb = cx0 >> 5;
    for (int i = tid; i < C1 * 12 * 4; i += 128) {
        int c = i / 48, r = (i / 4) % 12, w = i & 3;
        int gr = cy0 + r, gw = wb + w;
        uint32_t v = 0;
        if (gr < HPADIN && gw < 8) v = g_bits[((t * C1 + c) * HPADIN + gr) * 8 + gw];
        sb[c][r][w] = v;
    }
    if (tid < F1) { sminf[tid] = g_minwf[tid]; smaxf[tid] = g_maxwf[tid]; }
    __syncthreads();

    int px = px0 + threadIdx.x, py = py0 + threadIdx.y;
    if (px >= HP || py >= HP) return;
    int lr = 2 * threadIdx.y, lc = 2 * threadIdx.x;

    int a0 = shs[lr + 0][lc], a1 = shs[lr + 1][lc], a2 = shs[lr + 2][lc];
    int a3 = shs[lr + 3][lc], a4 = shs[lr + 4][lc], a5 = shs[lr + 5][lc];
    int b0 = shs[lr + 0][lc + 1], b1 = shs[lr + 1][lc + 1], b2 = shs[lr + 2][lc + 1];
    int b3 = shs[lr + 3][lc + 1], b4 = shs[lr + 4][lc + 1], b5 = shs[lr + 5][lc + 1];
    int cnt[2][2];
    int am = a1 + a2 + a3 + a4, bm = b1 + b2 + b3 + b4;
    cnt[0][0] = a0 + am; cnt[1][0] = am + a5;
    cnt[0][1] = b0 + bm; cnt[1][1] = bm + b5;
    int maxcnt = max(max(cnt[0][0], cnt[0][1]), max(cnt[1][0], cnt[1][1]));

    bool ap = (g_allpos != 0);
    uint32_t* pm = &g_pmask[(t * HPD + py + 1) * HPD + (px + 1)];

    if (ap && g_minwA * maxcnt > 15.001f) { *pm = FULLMASK; return; }
    if (ap && g_maxwA * maxcnt < 14.999f) { *pm = 0u; return; }

    uint32_t mask = 0;
    for (int f = 0; f < F1; f++) {
        float mn = sminf[f], mx = smaxf[f];
        int pooled;
        if (ap && mn * maxcnt > 15.001f) pooled = 1;
        else if (ap && mx * maxcnt < 14.999f) pooled = 0;
        else {
            pooled = 0;
            for (int dy = 0; dy < 2 && !pooled; dy++)
                for (int dx = 0; dx < 2 && !pooled; dx++) {
                    float pot = 0.f;
                    int off = lc + dx;
                    int w = off >> 5, s = off & 31;
                    for (int ch = 0; ch < C1; ch++) {
#pragma unroll
                        for (int i = 0; i < 5; i++) {
                            uint32_t lo = sb[ch][lr + dy + i][w];
                            uint32_t hi = sb[ch][lr + dy + i][w + 1];
                            uint32_t ck = __funnelshift_r(lo, hi, s);
                            const float* wp = &w1[((f * C1 + ch) * 5 + i) * 5];
#pragma unroll
                            for (int j = 0; j < 5; j++)
                                if ((ck >> j) & 1) pot += __ldg(wp + j);
                        }
                    }
                    pooled = (pot > 15.f) ? 1 : 0;
                }
        }
        mask |= ((uint32_t)pooled) << f;
    }
    *pm = mask;
}

// ---------------- K B1: classify (t,pixel) full vs deficient (+fill) ----------------
__global__ void kB1(float* __restrict__ out) {
    if (blockIdx.x >= 931) { fillBlk(out, blockIdx.x - 931u, B1_BEGIN); return; }
    int i = blockIdx.x * 256 + threadIdx.x;
    if (i >= TT * NPIX) return;
    int t = i / NPIX, pix = i % NPIX;
    int y = pix / HP, x = pix % HP;
    int s = 0;
#pragma unroll
    for (int dy = 0; dy < 3; dy++) {
        const uint32_t* row = &g_pmask[(t * HPD + y + dy) * HPD + x];
        s += __popc(row[0]) + __popc(row[1]) + __popc(row[2]);
    }
    if (s == TAPS) {
        g_maxv[i] = g_iMaxv; g_maxi[i] = g_iMaxi;
    } else {
        int slot = atomicAdd(&g_count, 1);
        g_list[slot] = i;
    }
}

// ---------------- K B2: deficient (t,pixel): all-250 pot + first-argmax (+fill) ----------------
__global__ void __launch_bounds__(256) kB2(float* __restrict__ out) {
    if (blockIdx.x >= 4096) { fillBlk(out, blockIdx.x - 4096u, B2_BEGIN); return; }
    __shared__ uint32_t pmask[9];
    __shared__ float rv[256];
    __shared__ int   ri[256];
    int cnt = g_count;
    int f = threadIdx.x;
    for (int e = blockIdx.x; e < cnt; e += 4096) {
        int id = g_list[e];
        int t = id / NPIX, pix = id % NPIX;
        int y = pix / HP, x = pix % HP;
        if (f < 9)
            pmask[f] = g_pmask[(t * HPD + y + f / 3) * HPD + x + f % 3];
        __syncthreads();
        float pot = g_S[f];
#pragma unroll
        for (int p = 0; p < 9; p++) {
            uint32_t mm = (~pmask[p]) & FULLMASK;
            while (mm) {
                int c = __ffs(mm) - 1; mm &= mm - 1;
                pot -= g_w2t[(c * 9 + p) * 256 + f];
            }
        }
        float pf = (f < F2 && pot > 10.f) ? pot : 0.f;
        rv[f] = pf; ri[f] = f;
        __syncthreads();
        for (int st = 128; st >= 1; st >>= 1) {
            if (f < st) {
                float o = rv[f + st]; int oi = ri[f + st];
                if (o > rv[f] || (o == rv[f] && oi < ri[f])) { rv[f] = o; ri[f] = oi; }
            }
            __syncthreads();
        }
        if (f == 0) { g_maxv[id] = rv[0]; g_maxi[id] = ri[0]; }
        __syncthreads();
    }
}

// ---------------- K B3: per-pixel earliest / winner feature / fired_last (+fill) ----------------
__global__ void kB3(float* __restrict__ out) {
    if (blockIdx.x >= 63) { fillBlk(out, blockIdx.x - 63u, B3_BEGIN); return; }
    int pix = blockIdx.x * 256 + threadIdx.x;
    if (pix >= NPIX) return;
    int cntf = 0, lastc = 0;
#pragma unroll
    for (int t = 0; t < TT; t++) {
        int c = (g_maxv[t * NPIX + pix] > 0.f) ? 1 : 0;
        cntf += c;
        if (t == TT - 1) lastc = c;
    }
    int e = TT - cntf; e = e < 0 ? 0 : (e > TT - 1 ? TT - 1 : e);
    g_win[pix] = g_maxi[e * NPIX + pix];
    g_fired[pix] = (uint8_t)lastc;
}

// ---------------- K B4: pot value of winning channel per (t,pixel) (+fill) ----------------
__global__ void kB4(float* __restrict__ out) {
    if (blockIdx.x >= 931) { fillBlk(out, blockIdx.x - 931u, B4_BEGIN); return; }
    int i = blockIdx.x * 256 + threadIdx.x;
    if (i >= TT * NPIX) return;
    int t = i / NPIX, pix = i % NPIX;
    float pv = 0.f;
    if (g_fired[pix]) {
        int win = g_win[pix];
        int y = pix / HP, x = pix % HP;
        uint32_t m[9];
        int s = 0;
#pragma unroll
        for (int p = 0; p < 9; p++) {
            m[p] = g_pmask[(t * HPD + y + p / 3) * HPD + x + p % 3];
            s += __popc(m[p]);
        }
        float pot = g_S[win];
        if (s != TAPS) {
#pragma unroll
            for (int p = 0; p < 9; p++) {            // (p outer, c ascending) == kB2 order
                uint32_t mm = (~m[p]) & FULLMASK;
                while (mm) {
                    int c = __ffs(mm) - 1; mm &= mm - 1;
                    pot -= g_w2t[(c * 9 + p) * 256 + win];
                }
            }
        }
        pv = (pot > 10.f) ? pot : 0.f;
    }
    g_pv[i] = pv;
}

// ---------------- K Fill: remaining zeros, flat ----------------
__global__ void __launch_bounds__(256) kFill(float* __restrict__ out) {
    unsigned i = REST_BEGIN + blockIdx.x * 256u + threadIdx.x;
    if (i < NQ2)
        __stcs((float4*)out + i, make_float4(0.f, 0.f, 0.f, 0.f));
}

// ---------------- K Scatter: sparse winner writes into zero-filled output ----------------
__global__ void kScatter(float* __restrict__ out) {
    int i = blockIdx.x * 256 + threadIdx.x;
    if (i >= TT * NPIX) return;
    int t = i / NPIX, pix = i % NPIX;
    float pv = g_pv[i];
    if (pv > 0.f) {
        int win = g_win[pix];
        size_t idx = ((size_t)(t * F2 + win)) * NPIX + pix;
        out[idx] = 1.0f;
        out[POT_OFF + idx] = pv;
    }
}

// ---------------- K B5a: earliest firing value + global vmax ----------------
__global__ void kB5a() {
    int pix = blockIdx.x * 256 + threadIdx.x;
    if (pix >= NPIX) return;
    int ns = 0;
#pragma unroll
    for (int t = 0; t < TT; t++) ns += (g_pv[t * NPIX + pix] > 0.f) ? 1 : 0;
    int e = TT - ns; e = e < 0 ? 0 : (e > TT - 1 ? TT - 1 : e);
    float val = g_pv[e * NPIX + pix];
    g_val[pix] = val;
    if (ns > 0) atomicMax(&g_vmaxbits, __float_as_int(val));
}

// ---------------- K B5b: per-pixel totals ----------------
__global__ void kB5b() {
    int pix = blockIdx.x * 256 + threadIdx.x;
    if (pix >= NPIX) return;
    float v = __int_as_float(g_vmaxbits) * 15.0f;
    float w = g_val[pix] + v;
    float tot = 0.f;
#pragma unroll
    for (int t = 0; t < TT; t++)
        if (g_pv[t * NPIX + pix] > 0.f) tot += w;
    g_total[pix] = tot;
}

// ---------------- K B6: k-winners ----------------
__global__ void __launch_bounds__(1024) kB6(float* __restrict__ outw) {
    __shared__ unsigned long long red[1024];
    __shared__ int winfo[3];
    int tid = threadIdx.x;
    unsigned kill = 0;
    for (int r = 0; r < 8; r++) {
        unsigned long long best = 0;
        for (int k = 0; k < 16; k++) {
            int e = tid * 16 + k;
            if (e < NPIX && !((kill >> k) & 1u)) {
                float tv = g_total[e];
                if (tv > 0.f) {
                    unsigned flat = (unsigned)(g_win[e] * NPIX + e);
                    unsigned long long key =
                        ((unsigned long long)__float_as_uint(tv) << 32) | (0xFFFFFFFFu - flat);
                    if (key > best) best = key;
                }
            }
        }
        red[tid] = best;
        __syncthreads();
        for (int st = 512; st >= 1; st >>= 1) {
            if (tid < st) {
                unsigned long long o = red[tid + st];
                if (o > red[tid]) red[tid] = o;
            }
            __syncthreads();
        }
        if (tid == 0) {
            unsigned long long b = red[0];
            if (b == 0) {
                winfo[0] = -1;
                outw[r * 3] = -1.f; outw[r * 3 + 1] = -1.f; outw[r * 3 + 2] = -1.f;
            } else {
                unsigned flat = 0xFFFFFFFFu - (unsigned)(b & 0xFFFFFFFFu);
                int c = flat / NPIX, pix = flat % NPIX;
                winfo[0] = c; winfo[1] = pix / HP; winfo[2] = pix % HP;
                outw[r * 3] = (float)c;
                outw[r * 3 + 1] = (float)winfo[1];
                outw[r * 3 + 2] = (float)winfo[2];
            }
        }
        __syncthreads();
        int wc = winfo[0];
        if (wc >= 0) {
            int wy = winfo[1], wx = winfo[2];
            for (int k = 0; k < 16; k++) {
                int e = tid * 16 + k;
                if (e < NPIX) {
                    int y = e / HP, x = e % HP;
                    if (g_win[e] == wc || (abs(y - wy) <= 1 && abs(x - wx) <= 1))
                        kill |= (1u << k);
                }
            }
        }
        __syncthreads();
    }
}

// ---------------- host launcher (R14 topology + in-kernel fill chunks) ----------------
extern "C" void kernel_launch(void* const* d_in, const int* in_sizes, int n_in,
                              void* d_out, int out_size) {
    const int*   inp = (const int*)d_in[0];
    const float* w1  = (const float*)d_in[2];
    const float* w2  = (const float*)d_in[3];
    float* out = (float*)d_out;

    cudaStream_t s2;
    cudaEvent_t evFork, evJoin;
    cudaStreamCreateWithFlags(&s2, cudaStreamNonBlocking);
    cudaEventCreateWithFlags(&evFork, cudaEventDisableTiming);
    cudaEventCreateWithFlags(&evJoin, cudaEventDisableTiming);

    kFuse0<<<4351 + F0_FILLB, 256>>>(inp, w1, w2, out);
    kPrep2<<<1, 256>>>();
    dim3 gA2(4, 32, TT + A2_FILLZ), bA2(32, 4);
    kA2<<<gA2, bA2>>>(w1, out);
    kB1<<<931 + B1_FILLB, 256>>>(out);
    kB2<<<4096 + B2_FILLB, 256>>>(out);
    kB3<<<63 + B3_FILLB, 256>>>(out);
    kB4<<<931 + B4_FILLB, 256>>>(out);

    // fork: side stream computes totals + k-winners while main finishes the fill
    cudaEventRecord(evFork, 0);
    cudaStreamWaitEvent(s2, evFork, 0);
    kB5a<<<(NPIX + 255) / 256, 256, 0, s2>>>();
    kB5b<<<(NPIX + 255) / 256, 256, 0, s2>>>();
    kB6<<<1, 1024, 0, s2>>>(out + WIN_OFF);
    cudaEventRecord(evJoin, s2);

    unsigned rest = NQ2 - REST_BEGIN;                  // 21378892 float4
    kFill<<<(rest + 255) / 256, 256>>>(out);
    kScatter<<<(TT * NPIX + 255) / 256, 256>>>(out);

    cudaStreamWaitEvent(0, evJoin, 0);

    cudaStreamDestroy(s2);
    cudaEventDestroy(evFork);
    cudaEventDestroy(evJoin);
}